// round 4
// baseline (speedup 1.0000x reference)
#include <cuda_runtime.h>
#include <cuda_bf16.h>
#include <math.h>
#include <stdint.h>

// Problem constants (fixed shapes from setup_inputs)
#define BSZ 8
#define SRC 512
#define TGT 256
#define HID 1024
#define TV  15000
#define VOC 20000
#define BT  (BSZ*TGT)   // 2048
#define K2  3072        // split-extended K: [hi|hi|lo] x [hi|lo|hi]
#define EPSF 1.1920928955078125e-7f
#define NEG_BIG -1000000000.0f

// ---------------------------------------------------------------------------
// Scratch (device globals; no allocations allowed)
// ---------------------------------------------------------------------------
__device__ float g_Q[BT * HID];          // gelu(feature @ W_q^T + b_q) fp32
__device__ float g_att[BT * SRC];        // raw Q.K^T (pre-scale)
__device__ float g_pexp[BT * SRC];       // exp(pointer_atten)
__device__ float4 g_rowc[BT];            // {gate, c1, c2, t2default}
__device__ float g_lse[BT];              // logsumexp of logits per row
__device__ int   g_leader[BSZ * SRC];    // first-occurrence index per (b,s)

// bf16 split-concatenated operands (K2 = 3072)
__device__ __nv_bfloat16 gA2[BT  * K2];          // feature: [Ah|Ah|Al]
__device__ __nv_bfloat16 gB2[HID * K2];          // W_q:     [Bh|Bl|Bh]
__device__ __nv_bfloat16 gM2[BSZ * SRC * K2];    // memory:  [Mh|Ml|Mh]
__device__ __nv_bfloat16 gQ2[BT  * K2];          // Q:       [Qh|Qh|Ql]

// ---------------------------------------------------------------------------
// PTX helpers — target-generic only (compute_103-safe): cp.async, ldmatrix, mma.sync
// ---------------------------------------------------------------------------
__device__ __forceinline__ uint32_t s2u(const void* p) {
    uint32_t a;
    asm("{ .reg .u64 t; cvta.to.shared.u64 t, %1; cvt.u32.u64 %0, t; }" : "=r"(a) : "l"(p));
    return a;
}
__device__ __forceinline__ void cp16(uint32_t dst, const void* src) {
    asm volatile("cp.async.cg.shared.global [%0], [%1], 16;" :: "r"(dst), "l"(src));
}
#define CP_COMMIT() asm volatile("cp.async.commit_group;" ::: "memory")
#define CP_WAIT0()  asm volatile("cp.async.wait_group 0;"  ::: "memory")

__device__ __forceinline__ void ldm_x4(uint32_t* r, uint32_t addr) {
    asm volatile("ldmatrix.sync.aligned.m8n8.x4.shared.b16 {%0,%1,%2,%3}, [%4];"
                 : "=r"(r[0]), "=r"(r[1]), "=r"(r[2]), "=r"(r[3]) : "r"(addr));
}
__device__ __forceinline__ void mma16816(float* c, const uint32_t* a, uint32_t b0, uint32_t b1) {
    asm volatile("mma.sync.aligned.m16n8k16.row.col.f32.bf16.bf16.f32 "
        "{%0,%1,%2,%3}, {%4,%5,%6,%7}, {%8,%9}, {%0,%1,%2,%3};"
        : "+f"(c[0]), "+f"(c[1]), "+f"(c[2]), "+f"(c[3])
        : "r"(a[0]), "r"(a[1]), "r"(a[2]), "r"(a[3]), "r"(b0), "r"(b1));
}

#define PITCH  40                    // bf16 elems per smem row (32 data + 8 pad)
#define STAGE_B (128 * PITCH * 2)    // bytes per tile stage = 10240
#define NCHUNK (K2 / 32)             // 96

__device__ __forceinline__ uint32_t pack2(float a, float b) {
    unsigned short ha = __bfloat16_as_ushort(__float2bfloat16_rn(a));
    unsigned short hb = __bfloat16_as_ushort(__float2bfloat16_rn(b));
    return (uint32_t)ha | ((uint32_t)hb << 16);
}

// ---------------------------------------------------------------------------
// Split kernel: fp32 -> concatenated hi/lo bf16 planes (K -> K2)
// ---------------------------------------------------------------------------
__global__ __launch_bounds__(256) void k_split(
    const float* __restrict__ f, const float* __restrict__ w, const float* __restrict__ m)
{
    const int NA4 = BT * HID / 4, NB4 = HID * HID / 4, NM4 = BSZ * SRC * HID / 4;
    const int i = blockIdx.x * 256 + threadIdx.x;
    if (i >= NA4 + NB4 + NM4) return;

    const float4* src; __nv_bfloat16* dst; int off; int isA;
    if (i < NA4)            { src = (const float4*)f; dst = gA2; off = i;             isA = 1; }
    else if (i < NA4 + NB4) { src = (const float4*)w; dst = gB2; off = i - NA4;       isA = 0; }
    else                    { src = (const float4*)m; dst = gM2; off = i - NA4 - NB4; isA = 0; }

    const int row = off >> 8;          // 256 float4 per 1024-wide row
    const int k4  = off & 255;
    const float4 v = src[off];
    const float xs[4] = {v.x, v.y, v.z, v.w};
    float hs[4], ls[4];
#pragma unroll
    for (int j = 0; j < 4; j++) {
        hs[j] = __bfloat162float(__float2bfloat16_rn(xs[j]));
        ls[j] = xs[j] - hs[j];
    }
    const uint2 HP = make_uint2(pack2(hs[0], hs[1]), pack2(hs[2], hs[3]));
    const uint2 LP = make_uint2(pack2(ls[0], ls[1]), pack2(ls[2], ls[3]));
    __nv_bfloat16* d = dst + (size_t)row * K2 + k4 * 4;
    if (isA) {   // [hi | hi | lo]
        *(uint2*)(d)        = HP;
        *(uint2*)(d + 1024) = HP;
        *(uint2*)(d + 2048) = LP;
    } else {     // [hi | lo | hi]
        *(uint2*)(d)        = HP;
        *(uint2*)(d + 1024) = LP;
        *(uint2*)(d + 2048) = HP;
    }
}

// ---------------------------------------------------------------------------
// GEMM core: C[128x128] = A[128xK2] . B[128xK2]^T  (both K-contiguous bf16)
// 256 threads = 8 warps (2 along M x 4 along N), warp tile 64x32,
// cp.async double-buffered, ldmatrix + mma.sync m16n8k16 bf16.
// ---------------------------------------------------------------------------
__device__ __forceinline__ void gemm_core(
    const __nv_bfloat16* __restrict__ Agl,   // + m0*K2
    const __nv_bfloat16* __restrict__ Bgl,   // + n0*K2
    __nv_bfloat16* As, __nv_bfloat16* Bs,    // [2][128][PITCH] each
    float c[4][4][4])
{
    const int tid  = threadIdx.x;
    const int lane = tid & 31;
    const int wid  = tid >> 5;
    const int wm   = (wid & 1) * 64;
    const int wn   = (wid >> 1) * 32;
    const uint32_t sa = s2u(As), sb = s2u(Bs);

#pragma unroll
    for (int mt = 0; mt < 4; mt++)
#pragma unroll
        for (int nt = 0; nt < 4; nt++)
#pragma unroll
            for (int j = 0; j < 4; j++) c[mt][nt][j] = 0.f;

    // stage loader: 128 rows x 32 cols bf16 per operand = 512 x 16B chunks
    const int r0 = tid >> 2, c16 = tid & 3;
    const int r1 = (tid + 256) >> 2, c16b = (tid + 256) & 3;

#define LOAD_STAGE(buf, kc) do { \
    const __nv_bfloat16* a_ = Agl + (kc) * 32; \
    const __nv_bfloat16* b_ = Bgl + (kc) * 32; \
    cp16(sa + (buf)*STAGE_B + r0*80 + c16*16,  a_ + (size_t)r0*K2 + c16*8); \
    cp16(sa + (buf)*STAGE_B + r1*80 + c16b*16, a_ + (size_t)r1*K2 + c16b*8); \
    cp16(sb + (buf)*STAGE_B + r0*80 + c16*16,  b_ + (size_t)r0*K2 + c16*8); \
    cp16(sb + (buf)*STAGE_B + r1*80 + c16b*16, b_ + (size_t)r1*K2 + c16b*8); \
    } while (0)

    LOAD_STAGE(0, 0);
    CP_COMMIT();

    const uint32_t a_lane_row = wm + (lane & 15);
    const uint32_t a_lane_col = (lane >> 4) * 16;          // bytes
    const uint32_t b_lane_row = wn + ((lane >> 4) << 3) + (lane & 7);
    const uint32_t b_lane_col = ((lane >> 3) & 1) << 4;    // bytes

    for (int kc = 0; kc < NCHUNK; kc++) {
        CP_WAIT0();
        __syncthreads();
        if (kc + 1 < NCHUNK) {
            LOAD_STAGE((kc + 1) & 1, kc + 1);
            CP_COMMIT();
        }
        const uint32_t buf = (kc & 1) * STAGE_B;
#pragma unroll
        for (int ks = 0; ks < 2; ks++) {
            uint32_t af[4][4];
#pragma unroll
            for (int mt = 0; mt < 4; mt++)
                ldm_x4(af[mt], sa + buf + (a_lane_row + mt * 16) * 80 + ks * 32 + a_lane_col);
            uint32_t bf[2][4];
#pragma unroll
            for (int bt = 0; bt < 2; bt++)
                ldm_x4(bf[bt], sb + buf + (b_lane_row + bt * 16) * 80 + ks * 32 + b_lane_col);
#pragma unroll
            for (int mt = 0; mt < 4; mt++)
#pragma unroll
                for (int nt = 0; nt < 4; nt++)
                    mma16816(c[mt][nt], af[mt], bf[nt >> 1][(nt & 1) * 2], bf[nt >> 1][(nt & 1) * 2 + 1]);
        }
        __syncthreads();
    }
#undef LOAD_STAGE
}

// ---------------------------------------------------------------------------
// GEMM 1: Q = gelu(A2 . B2^T + bias); writes g_Q fp32 + gQ2 = [Qh|Qh|Ql]
// grid: (HID/128=8, BT/128=16), 256 threads
// ---------------------------------------------------------------------------
__global__ __launch_bounds__(256, 1) void k_mm1(const float* __restrict__ bias)
{
    __shared__ __align__(16) __nv_bfloat16 As[2 * 128 * PITCH];
    __shared__ __align__(16) __nv_bfloat16 Bs[2 * 128 * PITCH];
    const int m0 = blockIdx.y * 128, n0 = blockIdx.x * 128;
    float c[4][4][4];

    gemm_core(gA2 + (size_t)m0 * K2, gB2 + (size_t)n0 * K2, As, Bs, c);

    const int lane = threadIdx.x & 31, wid = threadIdx.x >> 5;
    const int wm = (wid & 1) * 64, wn = (wid >> 1) * 32;
#pragma unroll
    for (int mt = 0; mt < 4; mt++)
#pragma unroll
        for (int nt = 0; nt < 4; nt++)
#pragma unroll
            for (int h = 0; h < 2; h++) {
                const int row = m0 + wm + mt * 16 + (lane >> 2) + h * 8;
                const int col = n0 + wn + nt * 8 + (lane & 3) * 2;
                float q[2];
#pragma unroll
                for (int j = 0; j < 2; j++) {
                    const float v = c[mt][nt][h * 2 + j] + bias[col + j];
                    q[j] = 0.5f * v * (1.0f + erff(v * 0.70710678118654752f));
                }
                *(float2*)&g_Q[(size_t)row * HID + col] = make_float2(q[0], q[1]);
                float hh[2], ll[2];
#pragma unroll
                for (int j = 0; j < 2; j++) {
                    hh[j] = __bfloat162float(__float2bfloat16_rn(q[j]));
                    ll[j] = q[j] - hh[j];
                }
                const uint32_t HP = pack2(hh[0], hh[1]);
                const uint32_t LP = pack2(ll[0], ll[1]);
                __nv_bfloat16* d = gQ2 + (size_t)row * K2 + col;
                *(uint32_t*)(d)        = HP;
                *(uint32_t*)(d + 1024) = HP;
                *(uint32_t*)(d + 2048) = LP;
            }
}

// ---------------------------------------------------------------------------
// GEMM 2: att[b,t,s] = Q2[bt,:] . M2[b,s,:]
// grid: (SRC/128=4, TGT/128=2, BSZ), 256 threads
// ---------------------------------------------------------------------------
__global__ __launch_bounds__(256, 1) void k_mm2()
{
    __shared__ __align__(16) __nv_bfloat16 As[2 * 128 * PITCH];
    __shared__ __align__(16) __nv_bfloat16 Bs[2 * 128 * PITCH];
    const int b  = blockIdx.z;
    const int m0 = b * TGT + blockIdx.y * 128;   // global bt row
    const int n0 = blockIdx.x * 128;             // src col
    float c[4][4][4];

    gemm_core(gQ2 + (size_t)m0 * K2, gM2 + ((size_t)b * SRC + n0) * K2, As, Bs, c);

    const int lane = threadIdx.x & 31, wid = threadIdx.x >> 5;
    const int wm = (wid & 1) * 64, wn = (wid >> 1) * 32;
#pragma unroll
    for (int mt = 0; mt < 4; mt++)
#pragma unroll
        for (int nt = 0; nt < 4; nt++)
#pragma unroll
            for (int h = 0; h < 2; h++) {
                const int row = m0 + wm + mt * 16 + (lane >> 2) + h * 8;
                const int col = n0 + wn + nt * 8 + (lane & 3) * 2;
                *(float2*)&g_att[(size_t)row * SRC + col] =
                    make_float2(c[mt][nt][h * 2], c[mt][nt][h * 2 + 1]);
            }
}

// ---------------------------------------------------------------------------
// Kernel 3: per-(b,t) row: sentinel dot, mask, log_softmax over 513
// ---------------------------------------------------------------------------
__global__ __launch_bounds__(256) void k_softmax_row(
    const float* __restrict__ sentinel, const unsigned char* __restrict__ mask)
{
    const int bt = blockIdx.x;
    const int b = bt / TGT;
    const int tid = threadIdx.x;
    __shared__ float red[256];

    {
        const float4 qa = *(const float4*)(g_Q + (size_t)bt * HID + tid * 4);
        const float4 sa = *(const float4*)(sentinel + tid * 4);
        red[tid] = qa.x*sa.x + qa.y*sa.y + qa.z*sa.z + qa.w*sa.w;
    }
    __syncthreads();
    for (int o = 128; o > 0; o >>= 1) {
        if (tid < o) red[tid] += red[tid + o];
        __syncthreads();
    }
    const float v512 = red[0] * 0.03125f;
    __syncthreads();

    const int s0 = tid, s1 = tid + 256;
    float x0 = g_att[(size_t)bt * SRC + s0] * 0.03125f;
    float x1 = g_att[(size_t)bt * SRC + s1] * 0.03125f;
    if (mask[b * SRC + s0]) x0 = NEG_BIG;
    if (mask[b * SRC + s1]) x1 = NEG_BIG;

    red[tid] = fmaxf(fmaxf(x0, x1), v512);
    __syncthreads();
    for (int o = 128; o > 0; o >>= 1) {
        if (tid < o) red[tid] = fmaxf(red[tid], red[tid + o]);
        __syncthreads();
    }
    const float m = red[0];
    __syncthreads();

    float ls = expf(x0 - m) + expf(x1 - m);
    if (tid == 0) ls += expf(v512 - m);
    red[tid] = ls;
    __syncthreads();
    for (int o = 128; o > 0; o >>= 1) {
        if (tid < o) red[tid] += red[tid + o];
        __syncthreads();
    }
    const float lse = m + logf(red[0]);

    g_pexp[(size_t)bt * SRC + s0] = expf(x0 - lse);
    g_pexp[(size_t)bt * SRC + s1] = expf(x1 - lse);

    if (tid == 0) {
        const float g  = v512 - lse;
        const float eg = expf(g);
        const float c1 = log1pf(-eg + EPSF);
        const float c2 = logf(1.0f - eg + EPSF);
        const float t2d = (logf(EPSF) - c1) + c2;
        g_rowc[bt] = make_float4(g, c1, c2, t2d);
    }
}

// ---------------------------------------------------------------------------
// Kernel 4a: per-row logsumexp of logits (two-pass: max then sum)
// ---------------------------------------------------------------------------
__global__ __launch_bounds__(256) void k_lse(const float* __restrict__ logits)
{
    const int bt = blockIdx.x;
    const int tid = threadIdx.x;
    __shared__ float red[256];
    const float4* lrow = (const float4*)(logits + (size_t)bt * TV);

    float m = -3.402823466e38f;
    for (int i = tid; i < TV / 4; i += 256) {
        const float4 x = lrow[i];
        m = fmaxf(m, fmaxf(fmaxf(x.x, x.y), fmaxf(x.z, x.w)));
    }
    red[tid] = m;
    __syncthreads();
    for (int o = 128; o > 0; o >>= 1) {
        if (tid < o) red[tid] = fmaxf(red[tid], red[tid + o]);
        __syncthreads();
    }
    const float M = red[0];
    __syncthreads();

    float s = 0.f;
    for (int i = tid; i < TV / 4; i += 256) {
        const float4 x = lrow[i];
        s += __expf(x.x - M) + __expf(x.y - M) + __expf(x.z - M) + __expf(x.w - M);
    }
    red[tid] = s;
    __syncthreads();
    for (int o = 128; o > 0; o >>= 1) {
        if (tid < o) red[tid] += red[tid + o];
        __syncthreads();
    }
    if (tid == 0) g_lse[bt] = M + logf(red[0]);
}

// ---------------------------------------------------------------------------
// helpers
// ---------------------------------------------------------------------------
__device__ __forceinline__ float term2f(float pv, float c1, float c2, float t2d) {
    return (pv == 0.f) ? t2d : (logf(pv + EPSF) - c1) + c2;
}
__device__ __forceinline__ float lsexp2(float a, float bb) {
    const float mm = fmaxf(a, bb);
    const float d = fabsf(a - bb);
    return (d > 20.f) ? mm : mm + log1pf(__expf(-d));
}

// ---------------------------------------------------------------------------
// Kernel 4b: fully streaming default-path writer (assumes p == 0 everywhere)
// ---------------------------------------------------------------------------
__global__ __launch_bounds__(256) void k_default(
    const float* __restrict__ logits, float* __restrict__ out)
{
    const int bt = blockIdx.y;
    const int i4 = blockIdx.x * 256 + threadIdx.x;
    if (i4 >= VOC / 4) return;

    const float4 rc = g_rowc[bt];
    const float g = rc.x, t2d = rc.w;
    const float lse = g_lse[bt];
    float4 o;

    if (i4 < TV / 4) {
        const float4 l4 = ((const float4*)(logits + (size_t)bt * TV))[i4];
        o.x = lsexp2((l4.x - lse) + g, t2d);
        o.y = lsexp2((l4.y - lse) + g, t2d);
        o.z = lsexp2((l4.z - lse) + g, t2d);
        o.w = lsexp2((l4.w - lse) + g, t2d);
    } else {
        o.x = o.y = o.z = o.w = t2d;
    }
    ((float4*)(out + (size_t)bt * VOC))[i4] = o;
}

// ---------------------------------------------------------------------------
// Kernel 4c: duplicate resolution per batch
// ---------------------------------------------------------------------------
__global__ __launch_bounds__(512) void k_leader(const int* __restrict__ content)
{
    const int b = blockIdx.x;
    const int s = threadIdx.x;
    __shared__ int cv[SRC];
    cv[s] = content[b * SRC + s];
    __syncthreads();
    const int v = cv[s];
    int lead = s;
    for (int j = 0; j < SRC; j++) {
        if (cv[j] == v) { lead = j; break; }
    }
    g_leader[b * SRC + s] = lead;
}

// ---------------------------------------------------------------------------
// Kernel 4d: fixup of touched vocab entries
// ---------------------------------------------------------------------------
__global__ __launch_bounds__(512) void k_fixup(
    const float* __restrict__ logits, const int* __restrict__ content,
    float* __restrict__ out)
{
    const int bt = blockIdx.x;
    const int b = bt / TGT;
    const int s = threadIdx.x;
    __shared__ float ps[SRC];

    ps[s] = 0.f;
    __syncthreads();

    const int lead = g_leader[b * SRC + s];
    atomicAdd(&ps[lead], g_pexp[(size_t)bt * SRC + s]);
    __syncthreads();

    if (lead == s) {
        const int v = content[b * SRC + s];
        const float4 rc = g_rowc[bt];
        const float g = rc.x, c1 = rc.y, c2 = rc.z, t2d = rc.w;
        const float t2 = term2f(ps[s], c1, c2, t2d);
        float o;
        if (v < TV) {
            const float lse = g_lse[bt];
            const float t1 = (logits[(size_t)bt * TV + v] - lse) + g;
            o = lsexp2(t1, t2);
        } else {
            o = t2;
        }
        out[(size_t)bt * VOC + v] = o;
    }
}

// ---------------------------------------------------------------------------
extern "C" void kernel_launch(void* const* d_in, const int* in_sizes, int n_in,
                              void* d_out, int out_size)
{
    const float* logits   = (const float*)d_in[0];
    const float* feature  = (const float*)d_in[1];
    const float* memory   = (const float*)d_in[2];
    const float* W_q      = (const float*)d_in[3];
    const float* b_q      = (const float*)d_in[4];
    const float* sentinel = (const float*)d_in[5];
    const unsigned char* mask = (const unsigned char*)d_in[6];
    const int* content    = (const int*)d_in[7];
    float* out = (float*)d_out;

    (void)in_sizes; (void)n_in; (void)out_size;

    const int splitTot = (BT*HID + HID*HID + BSZ*SRC*HID) / 4;
    k_split<<<(splitTot + 255) / 256, 256>>>(feature, W_q, memory);
    k_mm1<<<dim3(HID / 128, BT / 128), 256>>>(b_q);
    k_mm2<<<dim3(SRC / 128, TGT / 128, BSZ), 256>>>();
    k_softmax_row<<<BT, 256>>>(sentinel, mask);
    k_lse<<<BT, 256>>>(logits);
    k_leader<<<BSZ, 512>>>(content);
    k_default<<<dim3((VOC / 4 + 255) / 256, BT), 256>>>(logits, out);
    k_fixup<<<BT, 512>>>(logits, content, out);
}

// round 5
// speedup vs baseline: 1.4190x; 1.4190x over previous
#include <cuda_runtime.h>
#include <cuda_bf16.h>
#include <math.h>
#include <stdint.h>

// Problem constants (fixed shapes from setup_inputs)
#define BSZ 8
#define SRC 512
#define TGT 256
#define HID 1024
#define TV  15000
#define VOC 20000
#define BT  (BSZ*TGT)   // 2048
#define K2  3072        // effective split K: hi.hi + hi.lo + lo.hi
#define NCH 48          // K2 / 64
#define EPSF 1.1920928955078125e-7f
#define NEG_BIG -1000000000.0f

// ---------------------------------------------------------------------------
// Scratch (device globals; no allocations allowed)
// ---------------------------------------------------------------------------
__device__ float g_Q[BT * HID];          // gelu(feature @ W_q^T + b_q) fp32
__device__ float g_att[BT * SRC];        // raw Q.K^T (pre-scale)
__device__ float g_pexp[BT * SRC];       // exp(pointer_atten)
__device__ float4 g_rowc[BT];            // {gate, c1, c2, t2default}
__device__ float g_lse[BT];              // logsumexp of logits per row
__device__ int   g_leader[BSZ * SRC];    // first-occurrence index per (b,s)

// bf16 hi/lo planes
__device__ __nv_bfloat16 gA_hi[BT * HID],  gA_lo[BT * HID];       // feature
__device__ __nv_bfloat16 gB_hi[HID * HID], gB_lo[HID * HID];      // W_q
__device__ __nv_bfloat16 gM_hi[BSZ*SRC*HID], gM_lo[BSZ*SRC*HID];  // memory
__device__ __nv_bfloat16 gQ_hi[BT * HID],  gQ_lo[BT * HID];       // gelu(Q)

// ---------------------------------------------------------------------------
// PTX helpers — target-generic only (compute_103-safe)
// ---------------------------------------------------------------------------
__device__ __forceinline__ uint32_t s2u(const void* p) {
    uint32_t a;
    asm("{ .reg .u64 t; cvta.to.shared.u64 t, %1; cvt.u32.u64 %0, t; }" : "=r"(a) : "l"(p));
    return a;
}
__device__ __forceinline__ void cp16(uint32_t dst, const void* src) {
    asm volatile("cp.async.cg.shared.global [%0], [%1], 16;" :: "r"(dst), "l"(src));
}
#define CP_COMMIT() asm volatile("cp.async.commit_group;" ::: "memory")

__device__ __forceinline__ void ldm_x4(uint32_t* r, uint32_t addr) {
    asm volatile("ldmatrix.sync.aligned.m8n8.x4.shared.b16 {%0,%1,%2,%3}, [%4];"
                 : "=r"(r[0]), "=r"(r[1]), "=r"(r[2]), "=r"(r[3]) : "r"(addr));
}
__device__ __forceinline__ void mma16816(float* c, const uint32_t* a, uint32_t b0, uint32_t b1) {
    asm volatile("mma.sync.aligned.m16n8k16.row.col.f32.bf16.bf16.f32 "
        "{%0,%1,%2,%3}, {%4,%5,%6,%7}, {%8,%9}, {%0,%1,%2,%3};"
        : "+f"(c[0]), "+f"(c[1]), "+f"(c[2]), "+f"(c[3])
        : "r"(a[0]), "r"(a[1]), "r"(a[2]), "r"(a[3]), "r"(b0), "r"(b1));
}

__device__ __forceinline__ uint32_t pack2(float a, float b) {
    unsigned short ha = __bfloat16_as_ushort(__float2bfloat16_rn(a));
    unsigned short hb = __bfloat16_as_ushort(__float2bfloat16_rn(b));
    return (uint32_t)ha | ((uint32_t)hb << 16);
}

#define ROWB 144                 // smem row bytes: 64 bf16 data + 8 pad
#define AST  (128 * ROWB)        // 18432 B per A stage

// ---------------------------------------------------------------------------
// Split kernel: fp32 -> hi/lo bf16 planes
// ---------------------------------------------------------------------------
__global__ __launch_bounds__(256) void k_split(
    const float* __restrict__ f, const float* __restrict__ w, const float* __restrict__ m)
{
    const int NA4 = BT * HID / 4, NB4 = HID * HID / 4, NM4 = BSZ * SRC * HID / 4;
    const int i = blockIdx.x * 256 + threadIdx.x;
    if (i >= NA4 + NB4 + NM4) return;

    const float4* src; __nv_bfloat16 *hi, *lo; int off;
    if (i < NA4)            { src = (const float4*)f; hi = gA_hi; lo = gA_lo; off = i; }
    else if (i < NA4 + NB4) { src = (const float4*)w; hi = gB_hi; lo = gB_lo; off = i - NA4; }
    else                    { src = (const float4*)m; hi = gM_hi; lo = gM_lo; off = i - NA4 - NB4; }

    const float4 v = src[off];
    const float xs[4] = {v.x, v.y, v.z, v.w};
    float hs[4], ls[4];
#pragma unroll
    for (int j = 0; j < 4; j++) {
        hs[j] = __bfloat162float(__float2bfloat16_rn(xs[j]));
        ls[j] = xs[j] - hs[j];
    }
    *(uint2*)&hi[(size_t)off * 4] = make_uint2(pack2(hs[0], hs[1]), pack2(hs[2], hs[3]));
    *(uint2*)&lo[(size_t)off * 4] = make_uint2(pack2(ls[0], ls[1]), pack2(ls[2], ls[3]));
}

// ---------------------------------------------------------------------------
// GEMM core: C[128 x NT] += sum over 3 segments of A . B^T (K=1024 each)
// 256 threads = 8 warps (2M x 4N). 4-stage cp.async pipeline, K-chunk 64.
// ---------------------------------------------------------------------------
template<int NT>
__device__ __forceinline__ void gemm_core2(
    const __nv_bfloat16* __restrict__ Ah, const __nv_bfloat16* __restrict__ Al,
    const __nv_bfloat16* __restrict__ Bh, const __nv_bfloat16* __restrict__ Bl,
    char* smem, float c[4][4][4])
{
    constexpr int NLDM = NT / 64;         // 2 (NT=128) or 1 (NT=64)
    constexpr int BST  = NT * ROWB;
    const int tid = threadIdx.x, lane = tid & 31, wid = tid >> 5;
    const int wm = (wid & 1) * 64, wn = (wid >> 1) * (NT / 4);
    const uint32_t sa = s2u(smem), sb = s2u(smem + 4 * AST);
    const int lr = tid >> 3, lc = tid & 7;

#pragma unroll
    for (int mt = 0; mt < 4; mt++)
#pragma unroll
        for (int nt = 0; nt < 4; nt++)
#pragma unroll
            for (int j = 0; j < 4; j++) c[mt][nt][j] = 0.f;

#define LSTG(st, kc) do { \
    const int seg_ = (kc) >> 4; const int off_ = ((kc) & 15) * 64; \
    const __nv_bfloat16* ap_ = (seg_ == 2) ? Al : Ah; \
    const __nv_bfloat16* bp_ = (seg_ == 1) ? Bl : Bh; \
    _Pragma("unroll") \
    for (int i_ = 0; i_ < 4; i_++) { \
        const int r_ = lr + 32 * i_; \
        cp16(sa + (st)*AST + r_*ROWB + lc*16, ap_ + (size_t)r_*HID + off_ + lc*8); } \
    _Pragma("unroll") \
    for (int i_ = 0; i_ < NT/32; i_++) { \
        const int r_ = lr + 32 * i_; \
        cp16(sb + (st)*BST + r_*ROWB + lc*16, bp_ + (size_t)r_*HID + off_ + lc*8); } \
    } while (0)

    LSTG(0, 0); CP_COMMIT();
    LSTG(1, 1); CP_COMMIT();
    LSTG(2, 2); CP_COMMIT();

    const uint32_t a_r = wm + (lane & 15);
    const uint32_t a_c = (lane >> 4) * 16;                 // bytes
    const uint32_t b_r = wn + ((lane >> 4) << 3) + (lane & 7);
    const uint32_t b_c = ((lane >> 3) & 1) << 4;           // bytes

    for (int kc = 0; kc < NCH; kc++) {
        asm volatile("cp.async.wait_group 2;" ::: "memory");
        __syncthreads();
        // load stage kc+3 into slot (kc+3)&3 (never the slot being computed);
        // the barrier above guarantees everyone finished reading slot (kc-1)&3
        if (kc + 3 < NCH) LSTG((kc + 3) & 3, kc + 3);
        CP_COMMIT();   // unconditional: keeps group count uniform for wait_group 2

        const uint32_t ab = sa + (kc & 3) * AST;
        const uint32_t bb = sb + (kc & 3) * BST;
#pragma unroll
        for (int ks = 0; ks < 4; ks++) {
            uint32_t af[4][4];
#pragma unroll
            for (int mt = 0; mt < 4; mt++)
                ldm_x4(af[mt], ab + (a_r + mt * 16) * ROWB + ks * 32 + a_c);
            uint32_t bfm[NLDM][4];
#pragma unroll
            for (int bt = 0; bt < NLDM; bt++)
                ldm_x4(bfm[bt], bb + (b_r + bt * 16) * ROWB + ks * 32 + b_c);
#pragma unroll
            for (int mt = 0; mt < 4; mt++)
#pragma unroll
                for (int nt = 0; nt < 2 * NLDM; nt++)
                    mma16816(c[mt][nt], af[mt],
                             bfm[nt >> 1][(nt & 1) * 2], bfm[nt >> 1][(nt & 1) * 2 + 1]);
        }
    }
#undef LSTG
}

// ---------------------------------------------------------------------------
// GEMM 1: Q = gelu(feature @ W_q^T + bias) -> g_Q fp32 + gQ_hi/gQ_lo
// grid (HID/128=8, BT/128=16), 256 threads, smem 144 KB
// ---------------------------------------------------------------------------
__global__ __launch_bounds__(256, 1) void k_mm1(const float* __restrict__ bias)
{
    extern __shared__ __align__(16) char smem[];
    const int m0 = blockIdx.y * 128, n0 = blockIdx.x * 128;
    float c[4][4][4];

    gemm_core2<128>(gA_hi + (size_t)m0 * HID, gA_lo + (size_t)m0 * HID,
                    gB_hi + (size_t)n0 * HID, gB_lo + (size_t)n0 * HID, smem, c);

    const int lane = threadIdx.x & 31, wid = threadIdx.x >> 5;
    const int wm = (wid & 1) * 64, wn = (wid >> 1) * 32;
#pragma unroll
    for (int mt = 0; mt < 4; mt++)
#pragma unroll
        for (int nt = 0; nt < 4; nt++)
#pragma unroll
            for (int h = 0; h < 2; h++) {
                const int row = m0 + wm + mt * 16 + (lane >> 2) + h * 8;
                const int col = n0 + wn + nt * 8 + (lane & 3) * 2;
                float q[2];
#pragma unroll
                for (int j = 0; j < 2; j++) {
                    const float v = c[mt][nt][h * 2 + j] + bias[col + j];
                    q[j] = 0.5f * v * (1.0f + erff(v * 0.70710678118654752f));
                }
                *(float2*)&g_Q[(size_t)row * HID + col] = make_float2(q[0], q[1]);
                float hh[2], ll[2];
#pragma unroll
                for (int j = 0; j < 2; j++) {
                    hh[j] = __bfloat162float(__float2bfloat16_rn(q[j]));
                    ll[j] = q[j] - hh[j];
                }
                *(uint32_t*)&gQ_hi[(size_t)row * HID + col] = pack2(hh[0], hh[1]);
                *(uint32_t*)&gQ_lo[(size_t)row * HID + col] = pack2(ll[0], ll[1]);
            }
}

// ---------------------------------------------------------------------------
// GEMM 2: att[b,t,s] = Q[bt,:] . memory[b,s,:]
// grid (SRC/64=8, TGT/128=2, BSZ=8) = 128 CTAs, 256 threads, smem 108 KB
// ---------------------------------------------------------------------------
__global__ __launch_bounds__(256, 1) void k_mm2()
{
    extern __shared__ __align__(16) char smem[];
    const int b  = blockIdx.z;
    const int m0 = b * TGT + blockIdx.y * 128;
    const int n0 = blockIdx.x * 64;
    float c[4][4][4];

    gemm_core2<64>(gQ_hi + (size_t)m0 * HID, gQ_lo + (size_t)m0 * HID,
                   gM_hi + ((size_t)b * SRC + n0) * HID,
                   gM_lo + ((size_t)b * SRC + n0) * HID, smem, c);

    const int lane = threadIdx.x & 31, wid = threadIdx.x >> 5;
    const int wm = (wid & 1) * 64, wn = (wid >> 1) * 16;
#pragma unroll
    for (int mt = 0; mt < 4; mt++)
#pragma unroll
        for (int nt = 0; nt < 2; nt++)
#pragma unroll
            for (int h = 0; h < 2; h++) {
                const int row = m0 + wm + mt * 16 + (lane >> 2) + h * 8;
                const int col = n0 + wn + nt * 8 + (lane & 3) * 2;
                *(float2*)&g_att[(size_t)row * SRC + col] =
                    make_float2(c[mt][nt][h * 2], c[mt][nt][h * 2 + 1]);
            }
}

// ---------------------------------------------------------------------------
// Kernel 3: per-(b,t) row: sentinel dot, mask, log_softmax over 513
// ---------------------------------------------------------------------------
__global__ __launch_bounds__(256) void k_softmax_row(
    const float* __restrict__ sentinel, const unsigned char* __restrict__ mask)
{
    const int bt = blockIdx.x;
    const int b = bt / TGT;
    const int tid = threadIdx.x;
    __shared__ float red[256];

    {
        const float4 qa = *(const float4*)(g_Q + (size_t)bt * HID + tid * 4);
        const float4 sa = *(const float4*)(sentinel + tid * 4);
        red[tid] = qa.x*sa.x + qa.y*sa.y + qa.z*sa.z + qa.w*sa.w;
    }
    __syncthreads();
    for (int o = 128; o > 0; o >>= 1) {
        if (tid < o) red[tid] += red[tid + o];
        __syncthreads();
    }
    const float v512 = red[0] * 0.03125f;
    __syncthreads();

    const int s0 = tid, s1 = tid + 256;
    float x0 = g_att[(size_t)bt * SRC + s0] * 0.03125f;
    float x1 = g_att[(size_t)bt * SRC + s1] * 0.03125f;
    if (mask[b * SRC + s0]) x0 = NEG_BIG;
    if (mask[b * SRC + s1]) x1 = NEG_BIG;

    red[tid] = fmaxf(fmaxf(x0, x1), v512);
    __syncthreads();
    for (int o = 128; o > 0; o >>= 1) {
        if (tid < o) red[tid] = fmaxf(red[tid], red[tid + o]);
        __syncthreads();
    }
    const float m = red[0];
    __syncthreads();

    float ls = expf(x0 - m) + expf(x1 - m);
    if (tid == 0) ls += expf(v512 - m);
    red[tid] = ls;
    __syncthreads();
    for (int o = 128; o > 0; o >>= 1) {
        if (tid < o) red[tid] += red[tid + o];
        __syncthreads();
    }
    const float lse = m + logf(red[0]);

    g_pexp[(size_t)bt * SRC + s0] = expf(x0 - lse);
    g_pexp[(size_t)bt * SRC + s1] = expf(x1 - lse);

    if (tid == 0) {
        const float g  = v512 - lse;
        const float eg = expf(g);
        const float c1 = log1pf(-eg + EPSF);
        const float c2 = logf(1.0f - eg + EPSF);
        const float t2d = (logf(EPSF) - c1) + c2;
        g_rowc[bt] = make_float4(g, c1, c2, t2d);
    }
}

// ---------------------------------------------------------------------------
// helpers
// ---------------------------------------------------------------------------
__device__ __forceinline__ float term2f(float pv, float c1, float c2, float t2d) {
    return (pv == 0.f) ? t2d : (logf(pv + EPSF) - c1) + c2;
}
__device__ __forceinline__ float lsexp2(float a, float bb) {
    const float mm = fmaxf(a, bb);
    const float d = fabsf(a - bb);
    return (d > 20.f) ? mm : mm + log1pf(__expf(-d));
}

// ---------------------------------------------------------------------------
// Kernel 4: fused per-row lse + default output. One block per (b,t) row.
// Pass 1: max over logits row; pass 2: sum exp (row L1-resident);
// pass 3: write merged default output (p==0 everywhere; fixup patches later).
// ---------------------------------------------------------------------------
__global__ __launch_bounds__(512) void k_out(
    const float* __restrict__ logits, float* __restrict__ out)
{
    const int bt = blockIdx.x;
    const int tid = threadIdx.x;
    __shared__ float red[512];
    const float4* lrow = (const float4*)(logits + (size_t)bt * TV);

    float m = -3.402823466e38f;
    for (int i = tid; i < TV / 4; i += 512) {
        const float4 x = lrow[i];
        m = fmaxf(m, fmaxf(fmaxf(x.x, x.y), fmaxf(x.z, x.w)));
    }
    red[tid] = m;
    __syncthreads();
    for (int o = 256; o > 0; o >>= 1) {
        if (tid < o) red[tid] = fmaxf(red[tid], red[tid + o]);
        __syncthreads();
    }
    const float M = red[0];
    __syncthreads();

    float s = 0.f;
    for (int i = tid; i < TV / 4; i += 512) {
        const float4 x = lrow[i];
        s += __expf(x.x - M) + __expf(x.y - M) + __expf(x.z - M) + __expf(x.w - M);
    }
    red[tid] = s;
    __syncthreads();
    for (int o = 256; o > 0; o >>= 1) {
        if (tid < o) red[tid] += red[tid + o];
        __syncthreads();
    }
    const float lse = M + logf(red[0]);
    if (tid == 0) g_lse[bt] = lse;

    const float4 rc = g_rowc[bt];
    const float g = rc.x, t2d = rc.w;
    float4* orow = (float4*)(out + (size_t)bt * VOC);

    for (int i4 = tid; i4 < TV / 4; i4 += 512) {
        const float4 l4 = lrow[i4];
        float4 o;
        o.x = lsexp2((l4.x - lse) + g, t2d);
        o.y = lsexp2((l4.y - lse) + g, t2d);
        o.z = lsexp2((l4.z - lse) + g, t2d);
        o.w = lsexp2((l4.w - lse) + g, t2d);
        orow[i4] = o;
    }
    const float4 tv4 = make_float4(t2d, t2d, t2d, t2d);
    for (int i4 = TV / 4 + tid; i4 < VOC / 4; i4 += 512) orow[i4] = tv4;
}

// ---------------------------------------------------------------------------
// Kernel 5: duplicate resolution per batch
// ---------------------------------------------------------------------------
__global__ __launch_bounds__(512) void k_leader(const int* __restrict__ content)
{
    const int b = blockIdx.x;
    const int s = threadIdx.x;
    __shared__ int cv[SRC];
    cv[s] = content[b * SRC + s];
    __syncthreads();
    const int v = cv[s];
    int lead = s;
    for (int j = 0; j < SRC; j++) {
        if (cv[j] == v) { lead = j; break; }
    }
    g_leader[b * SRC + s] = lead;
}

// ---------------------------------------------------------------------------
// Kernel 6: fixup of touched vocab entries (runs after k_out)
// ---------------------------------------------------------------------------
__global__ __launch_bounds__(512) void k_fixup(
    const float* __restrict__ logits, const int* __restrict__ content,
    float* __restrict__ out)
{
    const int bt = blockIdx.x;
    const int b = bt / TGT;
    const int s = threadIdx.x;
    __shared__ float ps[SRC];

    ps[s] = 0.f;
    __syncthreads();

    const int lead = g_leader[b * SRC + s];
    atomicAdd(&ps[lead], g_pexp[(size_t)bt * SRC + s]);
    __syncthreads();

    if (lead == s) {
        const int v = content[b * SRC + s];
        const float4 rc = g_rowc[bt];
        const float g = rc.x, c1 = rc.y, c2 = rc.z, t2d = rc.w;
        const float t2 = term2f(ps[s], c1, c2, t2d);
        float o;
        if (v < TV) {
            const float lse = g_lse[bt];
            const float t1 = (logits[(size_t)bt * TV + v] - lse) + g;
            o = lsexp2(t1, t2);
        } else {
            o = t2;
        }
        out[(size_t)bt * VOC + v] = o;
    }
}

// ---------------------------------------------------------------------------
extern "C" void kernel_launch(void* const* d_in, const int* in_sizes, int n_in,
                              void* d_out, int out_size)
{
    const float* logits   = (const float*)d_in[0];
    const float* feature  = (const float*)d_in[1];
    const float* memory   = (const float*)d_in[2];
    const float* W_q      = (const float*)d_in[3];
    const float* b_q      = (const float*)d_in[4];
    const float* sentinel = (const float*)d_in[5];
    const unsigned char* mask = (const unsigned char*)d_in[6];
    const int* content    = (const int*)d_in[7];
    float* out = (float*)d_out;

    (void)in_sizes; (void)n_in; (void)out_size;

    const int smem1 = 4 * AST + 4 * 128 * ROWB;   // 147456
    const int smem2 = 4 * AST + 4 * 64 * ROWB;    // 110592
    cudaFuncSetAttribute(k_mm1, cudaFuncAttributeMaxDynamicSharedMemorySize, smem1);
    cudaFuncSetAttribute(k_mm2, cudaFuncAttributeMaxDynamicSharedMemorySize, smem2);

    const int splitTot = (BT*HID + HID*HID + BSZ*SRC*HID) / 4;
    k_split<<<(splitTot + 255) / 256, 256>>>(feature, W_q, memory);
    k_mm1<<<dim3(HID / 128, BT / 128), 256, smem1>>>(b_q);
    k_mm2<<<dim3(SRC / 64, TGT / 128, BSZ), 256, smem2>>>();
    k_softmax_row<<<BT, 256>>>(sentinel, mask);
    k_leader<<<BSZ, 512>>>(content);
    k_out<<<BT, 512>>>(logits, out);
    k_fixup<<<BT, 512>>>(logits, content, out);
}

// round 6
// speedup vs baseline: 1.5047x; 1.0604x over previous
#include <cuda_runtime.h>
#include <cuda_bf16.h>
#include <math.h>
#include <stdint.h>

// Problem constants (fixed shapes from setup_inputs)
#define BSZ 8
#define SRC 512
#define TGT 256
#define HID 1024
#define TV  15000
#define VOC 20000
#define BT  (BSZ*TGT)   // 2048
#define NCH 48          // effective K 3072 / 64
#define EPSF 1.1920928955078125e-7f
#define NEG_BIG -1000000000.0f

// ---------------------------------------------------------------------------
// Scratch (device globals; no allocations allowed)
// ---------------------------------------------------------------------------
__device__ float g_att[BT * SRC];        // raw Q.K^T (pre-scale)
__device__ float g_pexp[BT * SRC];       // exp(pointer_atten)
__device__ float4 g_rowc[BT];            // {gate, c1, c2, t2default}
__device__ float g_lse[BT];              // logsumexp of logits per row
__device__ int   g_leader[BSZ * SRC];    // first-occurrence index per (b,s)

// bf16 hi/lo planes
__device__ __nv_bfloat16 gA_hi[BT * HID],  gA_lo[BT * HID];       // feature
__device__ __nv_bfloat16 gB_hi[HID * HID], gB_lo[HID * HID];      // W_q
__device__ __nv_bfloat16 gM_hi[BSZ*SRC*HID], gM_lo[BSZ*SRC*HID];  // memory
__device__ __nv_bfloat16 gQ_hi[BT * HID],  gQ_lo[BT * HID];       // gelu(Q)

// ---------------------------------------------------------------------------
// PTX helpers — target-generic only (compute_103-safe)
// ---------------------------------------------------------------------------
__device__ __forceinline__ uint32_t s2u(const void* p) {
    uint32_t a;
    asm("{ .reg .u64 t; cvta.to.shared.u64 t, %1; cvt.u32.u64 %0, t; }" : "=r"(a) : "l"(p));
    return a;
}
__device__ __forceinline__ void cp16(uint32_t dst, const void* src) {
    asm volatile("cp.async.cg.shared.global [%0], [%1], 16;" :: "r"(dst), "l"(src));
}
#define CP_COMMIT() asm volatile("cp.async.commit_group;" ::: "memory")

__device__ __forceinline__ void ldm_x4(uint32_t* r, uint32_t addr) {
    asm volatile("ldmatrix.sync.aligned.m8n8.x4.shared.b16 {%0,%1,%2,%3}, [%4];"
                 : "=r"(r[0]), "=r"(r[1]), "=r"(r[2]), "=r"(r[3]) : "r"(addr));
}
__device__ __forceinline__ void mma16816(float* c, const uint32_t* a, uint32_t b0, uint32_t b1) {
    asm volatile("mma.sync.aligned.m16n8k16.row.col.f32.bf16.bf16.f32 "
        "{%0,%1,%2,%3}, {%4,%5,%6,%7}, {%8,%9}, {%0,%1,%2,%3};"
        : "+f"(c[0]), "+f"(c[1]), "+f"(c[2]), "+f"(c[3])
        : "r"(a[0]), "r"(a[1]), "r"(a[2]), "r"(a[3]), "r"(b0), "r"(b1));
}

__device__ __forceinline__ uint32_t pack2(float a, float b) {
    unsigned short ha = __bfloat16_as_ushort(__float2bfloat16_rn(a));
    unsigned short hb = __bfloat16_as_ushort(__float2bfloat16_rn(b));
    return (uint32_t)ha | ((uint32_t)hb << 16);
}

#define ROWB 144                 // smem row bytes: 64 bf16 data + 8 pad
#define AST  (128 * ROWB)        // 18432 B per A stage

// ---------------------------------------------------------------------------
// Split kernel: fp32 -> hi/lo bf16 planes
// ---------------------------------------------------------------------------
__global__ __launch_bounds__(256) void k_split(
    const float* __restrict__ f, const float* __restrict__ w, const float* __restrict__ m)
{
    const int NA4 = BT * HID / 4, NB4 = HID * HID / 4, NM4 = BSZ * SRC * HID / 4;
    const int i = blockIdx.x * 256 + threadIdx.x;
    if (i >= NA4 + NB4 + NM4) return;

    const float4* src; __nv_bfloat16 *hi, *lo; int off;
    if (i < NA4)            { src = (const float4*)f; hi = gA_hi; lo = gA_lo; off = i; }
    else if (i < NA4 + NB4) { src = (const float4*)w; hi = gB_hi; lo = gB_lo; off = i - NA4; }
    else                    { src = (const float4*)m; hi = gM_hi; lo = gM_lo; off = i - NA4 - NB4; }

    const float4 v = src[off];
    const float xs[4] = {v.x, v.y, v.z, v.w};
    float hs[4], ls[4];
#pragma unroll
    for (int j = 0; j < 4; j++) {
        hs[j] = __bfloat162float(__float2bfloat16_rn(xs[j]));
        ls[j] = xs[j] - hs[j];
    }
    *(uint2*)&hi[(size_t)off * 4] = make_uint2(pack2(hs[0], hs[1]), pack2(hs[2], hs[3]));
    *(uint2*)&lo[(size_t)off * 4] = make_uint2(pack2(ls[0], ls[1]), pack2(ls[2], ls[3]));
}

// ---------------------------------------------------------------------------
// GEMM core: C[128 x NT] += sum over 3 segments of A . B^T (K=1024 each)
// 256 threads = 8 warps (2M x 4N). 4-stage cp.async pipeline, K-chunk 64.
// ---------------------------------------------------------------------------
template<int NT>
__device__ __forceinline__ void gemm_core2(
    const __nv_bfloat16* __restrict__ Ah, const __nv_bfloat16* __restrict__ Al,
    const __nv_bfloat16* __restrict__ Bh, const __nv_bfloat16* __restrict__ Bl,
    char* smem, float c[4][4][4])
{
    constexpr int NLDM = NT / 64;         // 2 (NT=128) or 1 (NT=64)
    constexpr int BST  = NT * ROWB;
    const int tid = threadIdx.x, lane = tid & 31, wid = tid >> 5;
    const int wm = (wid & 1) * 64, wn = (wid >> 1) * (NT / 4);
    const uint32_t sa = s2u(smem), sb = s2u(smem + 4 * AST);
    const int lr = tid >> 3, lc = tid & 7;

#pragma unroll
    for (int mt = 0; mt < 4; mt++)
#pragma unroll
        for (int nt = 0; nt < 4; nt++)
#pragma unroll
            for (int j = 0; j < 4; j++) c[mt][nt][j] = 0.f;

#define LSTG(st, kc) do { \
    const int seg_ = (kc) >> 4; const int off_ = ((kc) & 15) * 64; \
    const __nv_bfloat16* ap_ = (seg_ == 2) ? Al : Ah; \
    const __nv_bfloat16* bp_ = (seg_ == 1) ? Bl : Bh; \
    _Pragma("unroll") \
    for (int i_ = 0; i_ < 4; i_++) { \
        const int r_ = lr + 32 * i_; \
        cp16(sa + (st)*AST + r_*ROWB + lc*16, ap_ + (size_t)r_*HID + off_ + lc*8); } \
    _Pragma("unroll") \
    for (int i_ = 0; i_ < NT/32; i_++) { \
        const int r_ = lr + 32 * i_; \
        cp16(sb + (st)*BST + r_*ROWB + lc*16, bp_ + (size_t)r_*HID + off_ + lc*8); } \
    } while (0)

    LSTG(0, 0); CP_COMMIT();
    LSTG(1, 1); CP_COMMIT();
    LSTG(2, 2); CP_COMMIT();

    const uint32_t a_r = wm + (lane & 15);
    const uint32_t a_c = (lane >> 4) * 16;                 // bytes
    const uint32_t b_r = wn + ((lane >> 4) << 3) + (lane & 7);
    const uint32_t b_c = ((lane >> 3) & 1) << 4;           // bytes

    for (int kc = 0; kc < NCH; kc++) {
        asm volatile("cp.async.wait_group 2;" ::: "memory");
        __syncthreads();
        if (kc + 3 < NCH) LSTG((kc + 3) & 3, kc + 3);
        CP_COMMIT();

        const uint32_t ab = sa + (kc & 3) * AST;
        const uint32_t bb = sb + (kc & 3) * BST;
#pragma unroll
        for (int ks = 0; ks < 4; ks++) {
            uint32_t af[4][4];
#pragma unroll
            for (int mt = 0; mt < 4; mt++)
                ldm_x4(af[mt], ab + (a_r + mt * 16) * ROWB + ks * 32 + a_c);
            uint32_t bfm[NLDM][4];
#pragma unroll
            for (int bt = 0; bt < NLDM; bt++)
                ldm_x4(bfm[bt], bb + (b_r + bt * 16) * ROWB + ks * 32 + b_c);
#pragma unroll
            for (int mt = 0; mt < 4; mt++)
#pragma unroll
                for (int nt = 0; nt < 2 * NLDM; nt++)
                    mma16816(c[mt][nt], af[mt],
                             bfm[nt >> 1][(nt & 1) * 2], bfm[nt >> 1][(nt & 1) * 2 + 1]);
        }
    }
#undef LSTG
}

// ---------------------------------------------------------------------------
// GEMM 1: Q = gelu(feature @ W_q^T + bias) -> gQ_hi/gQ_lo (bf16 planes only)
// grid (HID/128=8, BT/128=16), 256 threads, smem 144 KB
// ---------------------------------------------------------------------------
__global__ __launch_bounds__(256, 1) void k_mm1(const float* __restrict__ bias)
{
    extern __shared__ __align__(16) char smem[];
    const int m0 = blockIdx.y * 128, n0 = blockIdx.x * 128;
    float c[4][4][4];

    gemm_core2<128>(gA_hi + (size_t)m0 * HID, gA_lo + (size_t)m0 * HID,
                    gB_hi + (size_t)n0 * HID, gB_lo + (size_t)n0 * HID, smem, c);

    const int lane = threadIdx.x & 31, wid = threadIdx.x >> 5;
    const int wm = (wid & 1) * 64, wn = (wid >> 1) * 32;
#pragma unroll
    for (int mt = 0; mt < 4; mt++)
#pragma unroll
        for (int nt = 0; nt < 4; nt++)
#pragma unroll
            for (int h = 0; h < 2; h++) {
                const int row = m0 + wm + mt * 16 + (lane >> 2) + h * 8;
                const int col = n0 + wn + nt * 8 + (lane & 3) * 2;
                float q[2], hh[2], ll[2];
#pragma unroll
                for (int j = 0; j < 2; j++) {
                    const float v = c[mt][nt][h * 2 + j] + bias[col + j];
                    q[j] = 0.5f * v * (1.0f + erff(v * 0.70710678118654752f));
                    hh[j] = __bfloat162float(__float2bfloat16_rn(q[j]));
                    ll[j] = q[j] - hh[j];
                }
                *(uint32_t*)&gQ_hi[(size_t)row * HID + col] = pack2(hh[0], hh[1]);
                *(uint32_t*)&gQ_lo[(size_t)row * HID + col] = pack2(ll[0], ll[1]);
            }
}

// ---------------------------------------------------------------------------
// GEMM 2: att[b,t,s] = Q[bt,:] . memory[b,s,:]
// grid (SRC/64=8, TGT/128=2, BSZ=8) = 128 CTAs, 256 threads, smem 108 KB
// ---------------------------------------------------------------------------
__global__ __launch_bounds__(256, 1) void k_mm2()
{
    extern __shared__ __align__(16) char smem[];
    const int b  = blockIdx.z;
    const int m0 = b * TGT + blockIdx.y * 128;
    const int n0 = blockIdx.x * 64;
    float c[4][4][4];

    gemm_core2<64>(gQ_hi + (size_t)m0 * HID, gQ_lo + (size_t)m0 * HID,
                   gM_hi + ((size_t)b * SRC + n0) * HID,
                   gM_lo + ((size_t)b * SRC + n0) * HID, smem, c);

    const int lane = threadIdx.x & 31, wid = threadIdx.x >> 5;
    const int wm = (wid & 1) * 64, wn = (wid >> 1) * 16;
#pragma unroll
    for (int mt = 0; mt < 4; mt++)
#pragma unroll
        for (int nt = 0; nt < 2; nt++)
#pragma unroll
            for (int h = 0; h < 2; h++) {
                const int row = m0 + wm + mt * 16 + (lane >> 2) + h * 8;
                const int col = n0 + wn + nt * 8 + (lane & 3) * 2;
                *(float2*)&g_att[(size_t)row * SRC + col] =
                    make_float2(c[mt][nt][h * 2], c[mt][nt][h * 2 + 1]);
            }
}

// ---------------------------------------------------------------------------
// Kernel 3: per-(b,t) row: sentinel dot (from hi+lo planes), mask,
// log_softmax over 513, store exp(pointer_atten) + row constants.
// ---------------------------------------------------------------------------
__global__ __launch_bounds__(256) void k_softmax_row(
    const float* __restrict__ sentinel, const unsigned char* __restrict__ mask)
{
    const int bt = blockIdx.x;
    const int b = bt / TGT;
    const int tid = threadIdx.x;
    __shared__ float red[256];

    {
        const __nv_bfloat162* qh = (const __nv_bfloat162*)(gQ_hi + (size_t)bt * HID);
        const __nv_bfloat162* ql = (const __nv_bfloat162*)(gQ_lo + (size_t)bt * HID);
        const float4 sa = *(const float4*)(sentinel + tid * 4);
        const float2 h0 = __bfloat1622float2(qh[tid * 2]);
        const float2 h1 = __bfloat1622float2(qh[tid * 2 + 1]);
        const float2 l0 = __bfloat1622float2(ql[tid * 2]);
        const float2 l1 = __bfloat1622float2(ql[tid * 2 + 1]);
        red[tid] = (h0.x + l0.x) * sa.x + (h0.y + l0.y) * sa.y
                 + (h1.x + l1.x) * sa.z + (h1.y + l1.y) * sa.w;
    }
    __syncthreads();
    for (int o = 128; o > 0; o >>= 1) {
        if (tid < o) red[tid] += red[tid + o];
        __syncthreads();
    }
    const float v512 = red[0] * 0.03125f;
    __syncthreads();

    const int s0 = tid, s1 = tid + 256;
    float x0 = g_att[(size_t)bt * SRC + s0] * 0.03125f;
    float x1 = g_att[(size_t)bt * SRC + s1] * 0.03125f;
    if (mask[b * SRC + s0]) x0 = NEG_BIG;
    if (mask[b * SRC + s1]) x1 = NEG_BIG;

    red[tid] = fmaxf(fmaxf(x0, x1), v512);
    __syncthreads();
    for (int o = 128; o > 0; o >>= 1) {
        if (tid < o) red[tid] = fmaxf(red[tid], red[tid + o]);
        __syncthreads();
    }
    const float m = red[0];
    __syncthreads();

    float ls = __expf(x0 - m) + __expf(x1 - m);
    if (tid == 0) ls += __expf(v512 - m);
    red[tid] = ls;
    __syncthreads();
    for (int o = 128; o > 0; o >>= 1) {
        if (tid < o) red[tid] += red[tid + o];
        __syncthreads();
    }
    const float lse = m + logf(red[0]);

    g_pexp[(size_t)bt * SRC + s0] = __expf(x0 - lse);
    g_pexp[(size_t)bt * SRC + s1] = __expf(x1 - lse);

    if (tid == 0) {
        const float g  = v512 - lse;
        const float eg = expf(g);
        const float c1 = log1pf(-eg + EPSF);
        const float c2 = logf(1.0f - eg + EPSF);
        const float t2d = (logf(EPSF) - c1) + c2;
        g_rowc[bt] = make_float4(g, c1, c2, t2d);
    }
}

// ---------------------------------------------------------------------------
// helpers
// ---------------------------------------------------------------------------
__device__ __forceinline__ float term2f(float pv, float c1, float c2, float t2d) {
    return (pv == 0.f) ? t2d : (logf(pv + EPSF) - c1) + c2;
}
// branch-free fast logsumexp of 2 (plenty of precision headroom vs 1e-3)
__device__ __forceinline__ float lsexp2(float a, float bb) {
    const float mm = fmaxf(a, bb);
    const float d = fabsf(a - bb);
    return mm + __logf(1.0f + __expf(-d));
}

// ---------------------------------------------------------------------------
// Kernel 4: fused per-row lse + default output. One block (1024 thr) per row.
// ---------------------------------------------------------------------------
__global__ __launch_bounds__(1024) void k_out(
    const float* __restrict__ logits, float* __restrict__ out)
{
    const int bt = blockIdx.x;
    const int tid = threadIdx.x;
    const int lane = tid & 31, warp = tid >> 5;
    __shared__ float red[32];
    __shared__ float bcast;
    const float4* lrow = (const float4*)(logits + (size_t)bt * TV);

    // pass 1: max
    float m = -3.402823466e38f;
    for (int i = tid; i < TV / 4; i += 1024) {
        const float4 x = lrow[i];
        m = fmaxf(m, fmaxf(fmaxf(x.x, x.y), fmaxf(x.z, x.w)));
    }
#pragma unroll
    for (int o = 16; o > 0; o >>= 1) m = fmaxf(m, __shfl_xor_sync(0xffffffffu, m, o));
    if (lane == 0) red[warp] = m;
    __syncthreads();
    if (warp == 0) {
        m = red[lane];
#pragma unroll
        for (int o = 16; o > 0; o >>= 1) m = fmaxf(m, __shfl_xor_sync(0xffffffffu, m, o));
        if (lane == 0) bcast = m;
    }
    __syncthreads();
    const float M = bcast;

    // pass 2: sum of exp (row now L1/L2 resident)
    float s = 0.f;
    for (int i = tid; i < TV / 4; i += 1024) {
        const float4 x = lrow[i];
        s += __expf(x.x - M) + __expf(x.y - M) + __expf(x.z - M) + __expf(x.w - M);
    }
#pragma unroll
    for (int o = 16; o > 0; o >>= 1) s += __shfl_xor_sync(0xffffffffu, s, o);
    if (lane == 0) red[warp] = s;
    __syncthreads();
    if (warp == 0) {
        s = red[lane];
#pragma unroll
        for (int o = 16; o > 0; o >>= 1) s += __shfl_xor_sync(0xffffffffu, s, o);
        if (lane == 0) bcast = M + logf(s);
    }
    __syncthreads();
    const float lse = bcast;
    if (tid == 0) g_lse[bt] = lse;

    // pass 3: write default-merged output
    const float4 rc = g_rowc[bt];
    const float gl = rc.x - lse, t2d = rc.w;
    float4* orow = (float4*)(out + (size_t)bt * VOC);

    for (int i4 = tid; i4 < TV / 4; i4 += 1024) {
        const float4 l4 = lrow[i4];
        float4 o;
        o.x = lsexp2(l4.x + gl, t2d);
        o.y = lsexp2(l4.y + gl, t2d);
        o.z = lsexp2(l4.z + gl, t2d);
        o.w = lsexp2(l4.w + gl, t2d);
        orow[i4] = o;
    }
    const float4 tv4 = make_float4(t2d, t2d, t2d, t2d);
    for (int i4 = TV / 4 + tid; i4 < VOC / 4; i4 += 1024) orow[i4] = tv4;
}

// ---------------------------------------------------------------------------
// Kernel 5: duplicate resolution per batch
// ---------------------------------------------------------------------------
__global__ __launch_bounds__(512) void k_leader(const int* __restrict__ content)
{
    const int b = blockIdx.x;
    const int s = threadIdx.x;
    __shared__ int cv[SRC];
    cv[s] = content[b * SRC + s];
    __syncthreads();
    const int v = cv[s];
    int lead = s;
    for (int j = 0; j < SRC; j++) {
        if (cv[j] == v) { lead = j; break; }
    }
    g_leader[b * SRC + s] = lead;
}

// ---------------------------------------------------------------------------
// Kernel 6: fixup of touched vocab entries (runs after k_out)
// ---------------------------------------------------------------------------
__global__ __launch_bounds__(512) void k_fixup(
    const float* __restrict__ logits, const int* __restrict__ content,
    float* __restrict__ out)
{
    const int bt = blockIdx.x;
    const int b = bt / TGT;
    const int s = threadIdx.x;
    __shared__ float ps[SRC];

    ps[s] = 0.f;
    __syncthreads();

    const int lead = g_leader[b * SRC + s];
    atomicAdd(&ps[lead], g_pexp[(size_t)bt * SRC + s]);
    __syncthreads();

    if (lead == s) {
        const int v = content[b * SRC + s];
        const float4 rc = g_rowc[bt];
        const float g = rc.x, c1 = rc.y, c2 = rc.z, t2d = rc.w;
        const float t2 = term2f(ps[s], c1, c2, t2d);
        float o;
        if (v < TV) {
            const float lse = g_lse[bt];
            const float t1 = (logits[(size_t)bt * TV + v] - lse) + g;
            o = lsexp2(t1, t2);
        } else {
            o = t2;
        }
        out[(size_t)bt * VOC + v] = o;
    }
}

// ---------------------------------------------------------------------------
extern "C" void kernel_launch(void* const* d_in, const int* in_sizes, int n_in,
                              void* d_out, int out_size)
{
    const float* logits   = (const float*)d_in[0];
    const float* feature  = (const float*)d_in[1];
    const float* memory   = (const float*)d_in[2];
    const float* W_q      = (const float*)d_in[3];
    const float* b_q      = (const float*)d_in[4];
    const float* sentinel = (const float*)d_in[5];
    const unsigned char* mask = (const unsigned char*)d_in[6];
    const int* content    = (const int*)d_in[7];
    float* out = (float*)d_out;

    (void)in_sizes; (void)n_in; (void)out_size;

    const int smem1 = 4 * AST + 4 * 128 * ROWB;   // 147456
    const int smem2 = 4 * AST + 4 * 64 * ROWB;    // 110592
    cudaFuncSetAttribute(k_mm1, cudaFuncAttributeMaxDynamicSharedMemorySize, smem1);
    cudaFuncSetAttribute(k_mm2, cudaFuncAttributeMaxDynamicSharedMemorySize, smem2);

    const int splitTot = (BT*HID + HID*HID + BSZ*SRC*HID) / 4;
    k_split<<<(splitTot + 255) / 256, 256>>>(feature, W_q, memory);
    k_mm1<<<dim3(HID / 128, BT / 128), 256, smem1>>>(b_q);
    k_mm2<<<dim3(SRC / 64, TGT / 128, BSZ), 256, smem2>>>();
    k_softmax_row<<<BT, 256>>>(sentinel, mask);
    k_leader<<<BSZ, 512>>>(content);
    k_out<<<BT, 1024>>>(logits, out);
    k_fixup<<<BT, 512>>>(logits, content, out);
}

// round 7
// speedup vs baseline: 1.7848x; 1.1861x over previous
#include <cuda_runtime.h>
#include <cuda_bf16.h>
#include <math.h>
#include <stdint.h>

// Problem constants (fixed shapes from setup_inputs)
#define BSZ 8
#define SRC 512
#define TGT 256
#define HID 1024
#define TV  15000
#define VOC 20000
#define BT  (BSZ*TGT)   // 2048
#define NCH 48          // effective K 3072 / 64
#define NSTG 5          // cp.async pipeline stages
#define EPSF 1.1920928955078125e-7f
#define NEG_BIG -1000000000.0f

// ---------------------------------------------------------------------------
// Scratch (device globals; no allocations allowed)
// ---------------------------------------------------------------------------
__device__ float g_att[BT * SRC];        // raw Q.K^T (pre-scale)
__device__ float g_pexp[BT * SRC];       // exp(pointer_atten)
__device__ float4 g_rowc[BT];            // {gate, c1, c2, t2default}
__device__ int   g_leader[BSZ * SRC];    // first-occurrence index per (b,s)

// bf16 hi/lo planes
__device__ __nv_bfloat16 gA_hi[BT * HID],  gA_lo[BT * HID];       // feature
__device__ __nv_bfloat16 gB_hi[HID * HID], gB_lo[HID * HID];      // W_q
__device__ __nv_bfloat16 gM_hi[BSZ*SRC*HID], gM_lo[BSZ*SRC*HID];  // memory
__device__ __nv_bfloat16 gQ_hi[BT * HID],  gQ_lo[BT * HID];       // gelu(Q)

// ---------------------------------------------------------------------------
// PTX helpers — target-generic only (compute_103-safe)
// ---------------------------------------------------------------------------
__device__ __forceinline__ uint32_t s2u(const void* p) {
    uint32_t a;
    asm("{ .reg .u64 t; cvta.to.shared.u64 t, %1; cvt.u32.u64 %0, t; }" : "=r"(a) : "l"(p));
    return a;
}
__device__ __forceinline__ void cp16(uint32_t dst, const void* src) {
    asm volatile("cp.async.cg.shared.global [%0], [%1], 16;" :: "r"(dst), "l"(src));
}
#define CP_COMMIT() asm volatile("cp.async.commit_group;" ::: "memory")

__device__ __forceinline__ void ldm_x4(uint32_t* r, uint32_t addr) {
    asm volatile("ldmatrix.sync.aligned.m8n8.x4.shared.b16 {%0,%1,%2,%3}, [%4];"
                 : "=r"(r[0]), "=r"(r[1]), "=r"(r[2]), "=r"(r[3]) : "r"(addr));
}
__device__ __forceinline__ void mma16816(float* c, const uint32_t* a, uint32_t b0, uint32_t b1) {
    asm volatile("mma.sync.aligned.m16n8k16.row.col.f32.bf16.bf16.f32 "
        "{%0,%1,%2,%3}, {%4,%5,%6,%7}, {%8,%9}, {%0,%1,%2,%3};"
        : "+f"(c[0]), "+f"(c[1]), "+f"(c[2]), "+f"(c[3])
        : "r"(a[0]), "r"(a[1]), "r"(a[2]), "r"(a[3]), "r"(b0), "r"(b1));
}

__device__ __forceinline__ uint32_t pack2(float a, float b) {
    unsigned short ha = __bfloat16_as_ushort(__float2bfloat16_rn(a));
    unsigned short hb = __bfloat16_as_ushort(__float2bfloat16_rn(b));
    return (uint32_t)ha | ((uint32_t)hb << 16);
}

#define ROWB 144                 // smem row bytes: 64 bf16 data + 8 pad
#define AST  (128 * ROWB)        // 18432 B per A stage
#define NB_CONV ((BT*HID + HID*HID + BSZ*SRC*HID) / 4 / 256)   // 7168

// ---------------------------------------------------------------------------
// Split kernel: fp32 -> hi/lo bf16 planes. Last 8 blocks compute g_leader.
// ---------------------------------------------------------------------------
__global__ __launch_bounds__(256) void k_split(
    const float* __restrict__ f, const float* __restrict__ w,
    const float* __restrict__ m, const int* __restrict__ content)
{
    const int tid = threadIdx.x;
    if (blockIdx.x >= NB_CONV) {
        // leader role: first-occurrence index per (b,s)
        const int b = blockIdx.x - NB_CONV;
        __shared__ int cv[SRC];
        cv[tid] = content[b * SRC + tid];
        cv[tid + 256] = content[b * SRC + tid + 256];
        __syncthreads();
#pragma unroll
        for (int k = 0; k < 2; k++) {
            const int s = tid + k * 256;
            const int v = cv[s];
            int lead = s;
            for (int j = 0; j < SRC; j++)
                if (cv[j] == v) { lead = j; break; }
            g_leader[b * SRC + s] = lead;
        }
        return;
    }

    const int NA4 = BT * HID / 4, NB4 = HID * HID / 4;
    const int i = blockIdx.x * 256 + tid;

    const float4* src; __nv_bfloat16 *hi, *lo; int off;
    if (i < NA4)            { src = (const float4*)f; hi = gA_hi; lo = gA_lo; off = i; }
    else if (i < NA4 + NB4) { src = (const float4*)w; hi = gB_hi; lo = gB_lo; off = i - NA4; }
    else                    { src = (const float4*)m; hi = gM_hi; lo = gM_lo; off = i - NA4 - NB4; }

    const float4 v = src[off];
    const float xs[4] = {v.x, v.y, v.z, v.w};
    float hs[4], ls[4];
#pragma unroll
    for (int j = 0; j < 4; j++) {
        hs[j] = __bfloat162float(__float2bfloat16_rn(xs[j]));
        ls[j] = xs[j] - hs[j];
    }
    *(uint2*)&hi[(size_t)off * 4] = make_uint2(pack2(hs[0], hs[1]), pack2(hs[2], hs[3]));
    *(uint2*)&lo[(size_t)off * 4] = make_uint2(pack2(ls[0], ls[1]), pack2(ls[2], ls[3]));
}

// ---------------------------------------------------------------------------
// GEMM core: C[128 x NT] += sum over 3 segments of A . B^T (K=1024 each)
// 256 threads = 8 warps (2M x 4N). NSTG-stage cp.async pipeline, K-chunk 64.
// ---------------------------------------------------------------------------
template<int NT>
__device__ __forceinline__ void gemm_core2(
    const __nv_bfloat16* __restrict__ Ah, const __nv_bfloat16* __restrict__ Al,
    const __nv_bfloat16* __restrict__ Bh, const __nv_bfloat16* __restrict__ Bl,
    char* smem, float c[4][4][4])
{
    constexpr int NLDM = NT / 64;         // 2 (NT=128) or 1 (NT=64)
    constexpr int BST  = NT * ROWB;
    const int tid = threadIdx.x, lane = tid & 31, wid = tid >> 5;
    const int wm = (wid & 1) * 64, wn = (wid >> 1) * (NT / 4);
    const uint32_t sa = s2u(smem), sb = s2u(smem + NSTG * AST);
    const int lr = tid >> 3, lc = tid & 7;

#pragma unroll
    for (int mt = 0; mt < 4; mt++)
#pragma unroll
        for (int nt = 0; nt < 4; nt++)
#pragma unroll
            for (int j = 0; j < 4; j++) c[mt][nt][j] = 0.f;

#define LSTG(st, kc) do { \
    const int seg_ = (kc) >> 4; const int off_ = ((kc) & 15) * 64; \
    const __nv_bfloat16* ap_ = (seg_ == 2) ? Al : Ah; \
    const __nv_bfloat16* bp_ = (seg_ == 1) ? Bl : Bh; \
    _Pragma("unroll") \
    for (int i_ = 0; i_ < 4; i_++) { \
        const int r_ = lr + 32 * i_; \
        cp16(sa + (st)*AST + r_*ROWB + lc*16, ap_ + (size_t)r_*HID + off_ + lc*8); } \
    _Pragma("unroll") \
    for (int i_ = 0; i_ < NT/32; i_++) { \
        const int r_ = lr + 32 * i_; \
        cp16(sb + (st)*BST + r_*ROWB + lc*16, bp_ + (size_t)r_*HID + off_ + lc*8); } \
    } while (0)

#pragma unroll
    for (int p = 0; p < NSTG - 1; p++) { LSTG(p, p); CP_COMMIT(); }

    const uint32_t a_r = wm + (lane & 15);
    const uint32_t a_c = (lane >> 4) * 16;                 // bytes
    const uint32_t b_r = wn + ((lane >> 4) << 3) + (lane & 7);
    const uint32_t b_c = ((lane >> 3) & 1) << 4;           // bytes

    int st_c = 0, st_l = NSTG - 1;
    for (int kc = 0; kc < NCH; kc++) {
        asm volatile("cp.async.wait_group %0;" :: "n"(NSTG - 2) : "memory");
        __syncthreads();
        // slot st_l == compute slot of iteration kc-1; barrier above makes it safe
        if (kc + NSTG - 1 < NCH) LSTG(st_l, kc + NSTG - 1);
        CP_COMMIT();   // unconditional: uniform group count for wait_group

        const uint32_t ab = sa + st_c * AST;
        const uint32_t bb = sb + st_c * BST;
#pragma unroll
        for (int ks = 0; ks < 4; ks++) {
            uint32_t af[4][4];
#pragma unroll
            for (int mt = 0; mt < 4; mt++)
                ldm_x4(af[mt], ab + (a_r + mt * 16) * ROWB + ks * 32 + a_c);
            uint32_t bfm[NLDM][4];
#pragma unroll
            for (int bt = 0; bt < NLDM; bt++)
                ldm_x4(bfm[bt], bb + (b_r + bt * 16) * ROWB + ks * 32 + b_c);
#pragma unroll
            for (int mt = 0; mt < 4; mt++)
#pragma unroll
                for (int nt = 0; nt < 2 * NLDM; nt++)
                    mma16816(c[mt][nt], af[mt],
                             bfm[nt >> 1][(nt & 1) * 2], bfm[nt >> 1][(nt & 1) * 2 + 1]);
        }
        st_c = (st_c + 1 == NSTG) ? 0 : st_c + 1;
        st_l = (st_l + 1 == NSTG) ? 0 : st_l + 1;
    }
#undef LSTG
}

// ---------------------------------------------------------------------------
// GEMM 1: Q = gelu(feature @ W_q^T + bias) -> gQ_hi/gQ_lo
// grid (HID/128=8, BT/128=16), 256 threads
// ---------------------------------------------------------------------------
__global__ __launch_bounds__(256, 1) void k_mm1(const float* __restrict__ bias)
{
    extern __shared__ __align__(16) char smem[];
    const int m0 = blockIdx.y * 128, n0 = blockIdx.x * 128;
    float c[4][4][4];

    gemm_core2<128>(gA_hi + (size_t)m0 * HID, gA_lo + (size_t)m0 * HID,
                    gB_hi + (size_t)n0 * HID, gB_lo + (size_t)n0 * HID, smem, c);

    const int lane = threadIdx.x & 31, wid = threadIdx.x >> 5;
    const int wm = (wid & 1) * 64, wn = (wid >> 1) * 32;
#pragma unroll
    for (int mt = 0; mt < 4; mt++)
#pragma unroll
        for (int nt = 0; nt < 4; nt++)
#pragma unroll
            for (int h = 0; h < 2; h++) {
                const int row = m0 + wm + mt * 16 + (lane >> 2) + h * 8;
                const int col = n0 + wn + nt * 8 + (lane & 3) * 2;
                float q[2], hh[2], ll[2];
#pragma unroll
                for (int j = 0; j < 2; j++) {
                    const float v = c[mt][nt][h * 2 + j] + bias[col + j];
                    q[j] = 0.5f * v * (1.0f + erff(v * 0.70710678118654752f));
                    hh[j] = __bfloat162float(__float2bfloat16_rn(q[j]));
                    ll[j] = q[j] - hh[j];
                }
                *(uint32_t*)&gQ_hi[(size_t)row * HID + col] = pack2(hh[0], hh[1]);
                *(uint32_t*)&gQ_lo[(size_t)row * HID + col] = pack2(ll[0], ll[1]);
            }
}

// ---------------------------------------------------------------------------
// GEMM 2: att[b,t,s] = Q[bt,:] . memory[b,s,:]
// grid (SRC/64=8, TGT/128=2, BSZ=8) = 128 CTAs, 256 threads
// ---------------------------------------------------------------------------
__global__ __launch_bounds__(256, 1) void k_mm2()
{
    extern __shared__ __align__(16) char smem[];
    const int b  = blockIdx.z;
    const int m0 = b * TGT + blockIdx.y * 128;
    const int n0 = blockIdx.x * 64;
    float c[4][4][4];

    gemm_core2<64>(gQ_hi + (size_t)m0 * HID, gQ_lo + (size_t)m0 * HID,
                   gM_hi + ((size_t)b * SRC + n0) * HID,
                   gM_lo + ((size_t)b * SRC + n0) * HID, smem, c);

    const int lane = threadIdx.x & 31, wid = threadIdx.x >> 5;
    const int wm = (wid & 1) * 64, wn = (wid >> 1) * 16;
#pragma unroll
    for (int mt = 0; mt < 4; mt++)
#pragma unroll
        for (int nt = 0; nt < 2; nt++)
#pragma unroll
            for (int h = 0; h < 2; h++) {
                const int row = m0 + wm + mt * 16 + (lane >> 2) + h * 8;
                const int col = n0 + wn + nt * 8 + (lane & 3) * 2;
                *(float2*)&g_att[(size_t)row * SRC + col] =
                    make_float2(c[mt][nt][h * 2], c[mt][nt][h * 2 + 1]);
            }
}

// ---------------------------------------------------------------------------
// Kernel 3: per-(b,t) row: sentinel dot (hi+lo planes), mask,
// log_softmax over 513 -> g_pexp + row constants. Warp-shuffle reductions.
// ---------------------------------------------------------------------------
__global__ __launch_bounds__(256) void k_softmax_row(
    const float* __restrict__ sentinel, const unsigned char* __restrict__ mask)
{
    const int bt = blockIdx.x;
    const int b = bt / TGT;
    const int tid = threadIdx.x;
    const int lane = tid & 31, warp = tid >> 5;   // 8 warps
    __shared__ float red[8];
    __shared__ float bc;

    // sentinel dot partial
    float p;
    {
        const __nv_bfloat162* qh = (const __nv_bfloat162*)(gQ_hi + (size_t)bt * HID);
        const __nv_bfloat162* ql = (const __nv_bfloat162*)(gQ_lo + (size_t)bt * HID);
        const float4 sa = *(const float4*)(sentinel + tid * 4);
        const float2 h0 = __bfloat1622float2(qh[tid * 2]);
        const float2 h1 = __bfloat1622float2(qh[tid * 2 + 1]);
        const float2 l0 = __bfloat1622float2(ql[tid * 2]);
        const float2 l1 = __bfloat1622float2(ql[tid * 2 + 1]);
        p = (h0.x + l0.x) * sa.x + (h0.y + l0.y) * sa.y
          + (h1.x + l1.x) * sa.z + (h1.y + l1.y) * sa.w;
    }
#pragma unroll
    for (int o = 16; o > 0; o >>= 1) p += __shfl_xor_sync(0xffffffffu, p, o);
    if (lane == 0) red[warp] = p;
    __syncthreads();
    if (warp == 0) {
        float v = (lane < 8) ? red[lane] : 0.f;
#pragma unroll
        for (int o = 4; o > 0; o >>= 1) v += __shfl_xor_sync(0xffffffffu, v, o);
        if (lane == 0) bc = v;
    }
    __syncthreads();
    const float v512 = bc * 0.03125f;

    const int s0 = tid, s1 = tid + 256;
    float x0 = g_att[(size_t)bt * SRC + s0] * 0.03125f;
    float x1 = g_att[(size_t)bt * SRC + s1] * 0.03125f;
    if (mask[b * SRC + s0]) x0 = NEG_BIG;
    if (mask[b * SRC + s1]) x1 = NEG_BIG;

    // max
    float mm = fmaxf(fmaxf(x0, x1), v512);
#pragma unroll
    for (int o = 16; o > 0; o >>= 1) mm = fmaxf(mm, __shfl_xor_sync(0xffffffffu, mm, o));
    __syncthreads();   // red reuse guard
    if (lane == 0) red[warp] = mm;
    __syncthreads();
    if (warp == 0) {
        float v = (lane < 8) ? red[lane] : -3.402823466e38f;
#pragma unroll
        for (int o = 4; o > 0; o >>= 1) v = fmaxf(v, __shfl_xor_sync(0xffffffffu, v, o));
        if (lane == 0) bc = v;
    }
    __syncthreads();
    const float m = bc;

    // sum exp
    float ls = __expf(x0 - m) + __expf(x1 - m);
    if (tid == 0) ls += __expf(v512 - m);
#pragma unroll
    for (int o = 16; o > 0; o >>= 1) ls += __shfl_xor_sync(0xffffffffu, ls, o);
    __syncthreads();
    if (lane == 0) red[warp] = ls;
    __syncthreads();
    if (warp == 0) {
        float v = (lane < 8) ? red[lane] : 0.f;
#pragma unroll
        for (int o = 4; o > 0; o >>= 1) v += __shfl_xor_sync(0xffffffffu, v, o);
        if (lane == 0) bc = m + logf(v);
    }
    __syncthreads();
    const float lse = bc;

    g_pexp[(size_t)bt * SRC + s0] = __expf(x0 - lse);
    g_pexp[(size_t)bt * SRC + s1] = __expf(x1 - lse);

    if (tid == 0) {
        const float g  = v512 - lse;
        const float eg = expf(g);
        const float c1 = log1pf(-eg + EPSF);
        const float c2 = logf(1.0f - eg + EPSF);
        const float t2d = (logf(EPSF) - c1) + c2;
        g_rowc[bt] = make_float4(g, c1, c2, t2d);
    }
}

// ---------------------------------------------------------------------------
// helpers
// ---------------------------------------------------------------------------
__device__ __forceinline__ float term2f(float pv, float c1, float c2, float t2d) {
    return (pv == 0.f) ? t2d : (logf(pv + EPSF) - c1) + c2;
}
__device__ __forceinline__ float lsexp2(float a, float bb) {
    const float mm = fmaxf(a, bb);
    const float d = fabsf(a - bb);
    return mm + __logf(1.0f + __expf(-d));
}

// ---------------------------------------------------------------------------
// Kernel 4: fused per-row lse + default output + fixup patch.
// One block (1024 thr) per (b,t) row.
// lse without max-shift: logits are O(5), exp is safe in fp32; log_softmax is
// shift-invariant so this is mathematically identical.
// ---------------------------------------------------------------------------
__global__ __launch_bounds__(1024) void k_out(
    const float* __restrict__ logits, const int* __restrict__ content,
    float* __restrict__ out)
{
    const int bt = blockIdx.x;
    const int b = bt / TGT;
    const int tid = threadIdx.x;
    const int lane = tid & 31, warp = tid >> 5;
    __shared__ float ps[SRC];
    __shared__ float red[32];
    __shared__ float bc;
    const float4* lrow = (const float4*)(logits + (size_t)bt * TV);

    // scatter exp(atten) by leader into compact smem accumulator
    if (tid < SRC) ps[tid] = 0.f;
    __syncthreads();
    int lead = -1;
    if (tid < SRC) {
        lead = g_leader[b * SRC + tid];
        atomicAdd(&ps[lead], g_pexp[(size_t)bt * SRC + tid]);
    }

    // pass 1: sum of exp (no shift)
    float s = 0.f;
    for (int i = tid; i < TV / 4; i += 1024) {
        const float4 x = lrow[i];
        s += __expf(x.x) + __expf(x.y) + __expf(x.z) + __expf(x.w);
    }
#pragma unroll
    for (int o = 16; o > 0; o >>= 1) s += __shfl_xor_sync(0xffffffffu, s, o);
    if (lane == 0) red[warp] = s;
    __syncthreads();
    if (warp == 0) {
        s = red[lane];
#pragma unroll
        for (int o = 16; o > 0; o >>= 1) s += __shfl_xor_sync(0xffffffffu, s, o);
        if (lane == 0) bc = logf(s);
    }
    __syncthreads();
    const float lse = bc;

    // pass 2: streaming default-merged output (logits row L1-resident)
    const float4 rc = g_rowc[bt];
    const float g = rc.x, c1 = rc.y, c2 = rc.z, t2d = rc.w;
    const float gl = g - lse;
    float4* orow = (float4*)(out + (size_t)bt * VOC);

    for (int i4 = tid; i4 < TV / 4; i4 += 1024) {
        const float4 l4 = lrow[i4];
        float4 o;
        o.x = lsexp2(l4.x + gl, t2d);
        o.y = lsexp2(l4.y + gl, t2d);
        o.z = lsexp2(l4.z + gl, t2d);
        o.w = lsexp2(l4.w + gl, t2d);
        orow[i4] = o;
    }
    const float4 tv4 = make_float4(t2d, t2d, t2d, t2d);
    for (int i4 = TV / 4 + tid; i4 < VOC / 4; i4 += 1024) orow[i4] = tv4;
    __syncthreads();   // default writes done before patching

    // patch touched vocab entries (leaders only)
    if (tid < SRC && lead == tid) {
        const int v = content[b * SRC + tid];
        const float t2 = term2f(ps[tid], c1, c2, t2d);
        float o;
        if (v < TV) {
            const float t1 = logits[(size_t)bt * TV + v] + gl;
            o = lsexp2(t1, t2);
        } else {
            o = t2;
        }
        out[(size_t)bt * VOC + v] = o;
    }
}

// ---------------------------------------------------------------------------
extern "C" void kernel_launch(void* const* d_in, const int* in_sizes, int n_in,
                              void* d_out, int out_size)
{
    const float* logits   = (const float*)d_in[0];
    const float* feature  = (const float*)d_in[1];
    const float* memory   = (const float*)d_in[2];
    const float* W_q      = (const float*)d_in[3];
    const float* b_q      = (const float*)d_in[4];
    const float* sentinel = (const float*)d_in[5];
    const unsigned char* mask = (const unsigned char*)d_in[6];
    const int* content    = (const int*)d_in[7];
    float* out = (float*)d_out;

    (void)in_sizes; (void)n_in; (void)out_size;

    const int smem1 = NSTG * AST + NSTG * 128 * ROWB;   // 184320
    const int smem2 = NSTG * AST + NSTG * 64 * ROWB;    // 138240
    cudaFuncSetAttribute(k_mm1, cudaFuncAttributeMaxDynamicSharedMemorySize, smem1);
    cudaFuncSetAttribute(k_mm2, cudaFuncAttributeMaxDynamicSharedMemorySize, smem2);

    k_split<<<NB_CONV + BSZ, 256>>>(feature, W_q, memory, content);
    k_mm1<<<dim3(HID / 128, BT / 128), 256, smem1>>>(b_q);
    k_mm2<<<dim3(SRC / 64, TGT / 128, BSZ), 256, smem2>>>();
    k_softmax_row<<<BT, 256>>>(sentinel, mask);
    k_out<<<BT, 1024>>>(logits, content, out);
}